// round 13
// baseline (speedup 1.0000x reference)
#include <cuda_runtime.h>
#include <math.h>
#include <stdint.h>

#define POOL 7
#define CCH  256
#define HALF 128
#define MAXB 1024

typedef unsigned long long u64;

__device__ __forceinline__ u64 pk(float lo, float hi) {
    u64 r; asm("mov.b64 %0, {%1,%2};" : "=l"(r) : "f"(lo), "f"(hi)); return r;
}
__device__ __forceinline__ u64 fma2(u64 a, u64 b, u64 c) {
    u64 d; asm("fma.rn.f32x2 %0, %1, %2, %3;" : "=l"(d) : "l"(a), "l"(b), "l"(c)); return d;
}
__device__ __forceinline__ u64 mul2(u64 a, u64 b) {
    u64 d; asm("mul.rn.f32x2 %0, %1, %2;" : "=l"(d) : "l"(a), "l"(b)); return d;
}
__device__ __forceinline__ void unpk(u64 v, float& lo, float& hi) {
    asm("mov.b64 {%0,%1}, %2;" : "=f"(lo), "=f"(hi) : "l"(v));
}

// Per-box precomputed params. w[0..11] = WyP[4][3] (y-weights for pool-row
// pairs (2j,2j+1), j=3 duplicates row 6). w[12..32] = WxB[7][3] (x-weights
// broadcast in both halves). hdr = {cbase, H, Y0, lvl}.
struct __align__(16) BoxPre {
    int4 hdr;
    u64  w[34];     // 33 used + pad
};
__device__ BoxPre g_pre[MAXB];

// ---------------- Kernel 1: per-box precompute (1 warp per box) -------------
__global__ void __launch_bounds__(128) precompute_kernel(
    const float* __restrict__ boxes, int nboxes)
{
    const int warp = (blockIdx.x * blockDim.x + threadIdx.x) >> 5;
    const int lane = threadIdx.x & 31;
    if (warp >= nboxes) return;

    const float bf = __ldg(boxes + warp * 5 + 0);
    const float c1 = __ldg(boxes + warp * 5 + 1);
    const float c2 = __ldg(boxes + warp * 5 + 2);
    const float c3 = __ldg(boxes + warp * 5 + 3);
    const float c4 = __ldg(boxes + warp * 5 + 4);

    // roi level: 4 + log2(sqrt(h*w)/(224/1024)), round-half-even, clip [2,5]
    int lvl = (int)rintf(4.0f + log2f(sqrtf((c3 - c1) * (c4 - c2)) / 0.21875f));
    lvl = max(2, min(5, lvl));
    const int   H     = 1024 >> lvl;
    const float Hf    = (float)H;
    const float scale = 1.0f / (float)(1 << lvl);

    // _roi_align: rois cols (x1,y1,x2,y2): x from boxes cols 1,3; y from 2,4
    const float ax1 = c1 * scale, ay1 = c2 * scale;
    const float bw = fmaxf(c3 * scale - ax1, 1.0f) * (1.0f / POOL);
    const float bh = fmaxf(c4 * scale - ay1, 1.0f) * (1.0f / POOL);

    // Normalized coords * scale <= 0.25 => samples in [0,1.18] => Y0,X0 in {0,1}
    const int Y0 = (int)floorf(fminf(fmaxf(ay1 + 0.5f * bh, 0.0f), Hf - 1.0f));

    BoxPre& P = g_pre[warp];
    if (lane == 0) {
        P.hdr = make_int4((int)bf * (CCH * H * H), H, Y0, lvl);
    }

    if (lane < POOL) {
        const int   p  = lane;
        const float pc = (float)p + 0.5f;

        float wvy[3] = {0.f, 0.f, 0.f};
        {
            float y   = ay1 + pc * bh;
            float vy  = (y > -1.0f && y < Hf) ? 1.0f : 0.0f;
            float ycl = fminf(fmaxf(y, 0.0f), Hf - 1.0f);
            int   y0  = (int)floorf(ycl);
            float ly  = ycl - (float)y0;
            wvy[y0     - Y0] += vy * (1.0f - ly);
            wvy[y0 + 1 - Y0] += vy * ly;           // y0+1 <= 2 < H-1
        }
        float wvx[3] = {0.f, 0.f, 0.f};
        {
            float x   = ax1 + pc * bw;
            float vx  = (x > -1.0f && x < Hf) ? 1.0f : 0.0f;
            float xcl = fminf(fmaxf(x, 0.0f), Hf - 1.0f);
            int   x0  = (int)floorf(xcl);
            float lx  = xcl - (float)x0;
            wvx[x0    ] += vx * (1.0f - lx);
            wvx[x0 + 1] += vx * lx;                // x0+1 <= 2
        }

        float* wyf = (float*)&P.w[0];    // [4][3][2]
        float* wxf = (float*)&P.w[12];   // [7][3][2]
        if (p < 6) {
            const int j = p >> 1, h2 = p & 1;
            wyf[(j * 3 + 0) * 2 + h2] = wvy[0];
            wyf[(j * 3 + 1) * 2 + h2] = wvy[1];
            wyf[(j * 3 + 2) * 2 + h2] = wvy[2];
        } else {  // p == 6 -> pair (6,6): both halves
            wyf[(3 * 3 + 0) * 2 + 0] = wvy[0]; wyf[(3 * 3 + 0) * 2 + 1] = wvy[0];
            wyf[(3 * 3 + 1) * 2 + 0] = wvy[1]; wyf[(3 * 3 + 1) * 2 + 1] = wvy[1];
            wyf[(3 * 3 + 2) * 2 + 0] = wvy[2]; wyf[(3 * 3 + 2) * 2 + 1] = wvy[2];
        }
        wxf[(p * 3 + 0) * 2 + 0] = wvx[0]; wxf[(p * 3 + 0) * 2 + 1] = wvx[0];
        wxf[(p * 3 + 1) * 2 + 0] = wvx[1]; wxf[(p * 3 + 1) * 2 + 1] = wvx[1];
        wxf[(p * 3 + 2) * 2 + 0] = wvx[2]; wxf[(p * 3 + 2) * 2 + 1] = wvx[2];
    }
}

// ---------------- Kernel 2: main (2 blocks per box, 9 blocks/SM) ------------
__global__ void __launch_bounds__(HALF, 9) roi_align_kernel(
    const float* __restrict__ f2,
    const float* __restrict__ f3,
    const float* __restrict__ f4,
    const float* __restrict__ f5,
    float* __restrict__ out)
{
    __shared__ __align__(16) float stage[HALF * POOL * POOL];   // 25088 B

    const int box  = blockIdx.x >> 1;
    const int half = blockIdx.x & 1;
    const int tid  = threadIdx.x;
    const int wid  = tid >> 5;
    const int lane = tid & 31;

    const BoxPre& P = g_pre[box];
    const int4 hdr = __ldg(&P.hdr);          // {cbase, H, Y0, lvl}
    const int  H = hdr.y, Y0 = hdr.z, lvl = hdr.w;

    const float* fm = (lvl == 2) ? f2 : (lvl == 3) ? f3 : (lvl == 4) ? f4 : f5;
    const int c = half * HALF + tid;
    const float* base = fm + (long)hdr.x + (long)c * (H * H) + Y0 * H;

    // ---- Patch gather: 3 x LDG.128 issued immediately ----
    const float4 v0 = __ldg((const float4*)(base));
    const float4 v1 = __ldg((const float4*)(base + H));
    const float4 v2 = __ldg((const float4*)(base + 2 * H));

    // ---- Vectorized broadcast weight loads: 6 x LDG.128 for the 12 wy ----
    u64 wy[12];
    {
        const ulonglong2* wv = (const ulonglong2*)&P.w[0];
        #pragma unroll
        for (int i = 0; i < 6; i++) {
            ulonglong2 t = __ldg(wv + i);
            wy[2 * i]     = t.x;
            wy[2 * i + 1] = t.y;
        }
    }

    // ---- Broadcast-pack patch columns ----
    u64 vB[3][3];
    vB[0][0] = pk(v0.x, v0.x); vB[0][1] = pk(v0.y, v0.y); vB[0][2] = pk(v0.z, v0.z);
    vB[1][0] = pk(v1.x, v1.x); vB[1][1] = pk(v1.y, v1.y); vB[1][2] = pk(v1.z, v1.z);
    vB[2][0] = pk(v2.x, v2.x); vB[2][1] = pk(v2.y, v2.y); vB[2][2] = pk(v2.z, v2.z);

    // ---- Row-reduce: tP[j][c] = packed (t_c(2j), t_c(2j+1)) — 36 FFMA2 ----
    u64 tP[4][3];
    #pragma unroll
    for (int j = 0; j < 4; j++) {
        const u64 wy0 = wy[j * 3 + 0], wy1 = wy[j * 3 + 1], wy2 = wy[j * 3 + 2];
        tP[j][0] = fma2(wy0, vB[0][0], fma2(wy1, vB[1][0], mul2(wy2, vB[2][0])));
        tP[j][1] = fma2(wy0, vB[0][1], fma2(wy1, vB[1][1], mul2(wy2, vB[2][1])));
        tP[j][2] = fma2(wy0, vB[0][2], fma2(wy1, vB[1][2], mul2(wy2, vB[2][2])));
    }

    // ---- Col-reduce + store into this warp's stage chunk — 84 FFMA2 ----
    float* st = stage + tid * (POOL * POOL);
    #pragma unroll
    for (int px = 0; px < POOL; px++) {
        const u64 wx0 = __ldg(&P.w[12 + px * 3 + 0]);
        const u64 wx1 = __ldg(&P.w[12 + px * 3 + 1]);
        const u64 wx2 = __ldg(&P.w[12 + px * 3 + 2]);
        #pragma unroll
        for (int j = 0; j < 4; j++) {
            u64 o = fma2(wx0, tP[j][0], fma2(wx1, tP[j][1], mul2(wx2, tP[j][2])));
            float lo, hi; unpk(o, lo, hi);
            if (j < 3) {
                st[(2 * j)     * POOL + px] = lo;
                st[(2 * j + 1) * POOL + px] = hi;
            } else {
                st[6 * POOL + px] = lo;   // pair (6,6): halves identical
            }
        }
    }
    __syncwarp();

    // ---- Per-warp coalesced writeback (fire-and-forget STG.128) ----
    const float4* s4 = (const float4*)(stage + (wid * 32) * (POOL * POOL));
    float4*       o4 = (float4*)(out + ((long)box * CCH + half * HALF + wid * 32)
                                       * (POOL * POOL));
    #pragma unroll
    for (int k = 0; k < 13; k++) {
        const int idx = k * 32 + lane;
        if (idx < (32 * POOL * POOL) / 4)     // 392
            o4[idx] = s4[idx];
    }
}

extern "C" void kernel_launch(void* const* d_in, const int* in_sizes, int n_in,
                              void* d_out, int out_size)
{
    const float* boxes = (const float*)d_in[0];
    const float* f2    = (const float*)d_in[1];
    const float* f3    = (const float*)d_in[2];
    const float* f4    = (const float*)d_in[3];
    const float* f5    = (const float*)d_in[4];
    float*       out   = (float*)d_out;

    int nboxes = in_sizes[0] / 5;
    if (nboxes > MAXB) nboxes = MAXB;

    const int pre_blocks = (nboxes * 32 + 127) / 128;
    precompute_kernel<<<pre_blocks, 128>>>(boxes, nboxes);
    roi_align_kernel<<<2 * nboxes, HALF>>>(f2, f3, f4, f5, out);
}

// round 14
// speedup vs baseline: 1.1626x; 1.1626x over previous
#include <cuda_runtime.h>
#include <math.h>
#include <stdint.h>

#define POOL 7
#define CCH  256
#define HALF 128

typedef unsigned long long u64;

__device__ __forceinline__ u64 pk(float lo, float hi) {
    u64 r; asm("mov.b64 %0, {%1,%2};" : "=l"(r) : "f"(lo), "f"(hi)); return r;
}
__device__ __forceinline__ u64 fma2(u64 a, u64 b, u64 c) {
    u64 d; asm("fma.rn.f32x2 %0, %1, %2, %3;" : "=l"(d) : "l"(a), "l"(b), "l"(c)); return d;
}
__device__ __forceinline__ u64 mul2(u64 a, u64 b) {
    u64 d; asm("mul.rn.f32x2 %0, %1, %2;" : "=l"(d) : "l"(a), "l"(b)); return d;
}
__device__ __forceinline__ void unpk(u64 v, float& lo, float& hi) {
    asm("mov.b64 {%0,%1}, %2;" : "=f"(lo), "=f"(hi) : "l"(v));
}

__global__ void __launch_bounds__(HALF, 6) roi_align_kernel(
    const float* __restrict__ boxes,
    const float* __restrict__ f2,
    const float* __restrict__ f3,
    const float* __restrict__ f4,
    const float* __restrict__ f5,
    float* __restrict__ out)
{
    // Per-block box params (built by warp 0 only).
    // w[0..11]  = WyP[4][3]: y-weights for pool-row pairs (2j,2j+1), j=3 dups row 6.
    // w[12..32] = WxB[7][3]: x-weights broadcast into both halves.
    __shared__ int4 hdr_s;                                    // {cbase, H, Y0, lvl}
    __shared__ __align__(16) u64 w_s[34];
    __shared__ __align__(16) float stage[HALF * POOL * POOL]; // 25088 B

    const int box  = blockIdx.x >> 1;
    const int half = blockIdx.x & 1;
    const int tid  = threadIdx.x;
    const int wid  = tid >> 5;
    const int lane = tid & 31;

    // ---- Warp 0 only: box scalar chain + packed weight table ----
    if (wid == 0) {
        const float bf = __ldg(boxes + box * 5 + 0);
        const float c1 = __ldg(boxes + box * 5 + 1);
        const float c2 = __ldg(boxes + box * 5 + 2);
        const float c3 = __ldg(boxes + box * 5 + 3);
        const float c4 = __ldg(boxes + box * 5 + 4);

        // roi level: 4 + log2(sqrt(h*w)/(224/1024)), round-half-even, clip [2,5]
        int lvl = (int)rintf(4.0f + log2f(sqrtf((c3 - c1) * (c4 - c2)) / 0.21875f));
        lvl = max(2, min(5, lvl));
        const int   H     = 1024 >> lvl;
        const float Hf    = (float)H;
        const float scale = 1.0f / (float)(1 << lvl);

        // _roi_align: rois cols (x1,y1,x2,y2): x from boxes cols 1,3; y from 2,4
        const float ax1 = c1 * scale, ay1 = c2 * scale;
        const float bw = fmaxf(c3 * scale - ax1, 1.0f) * (1.0f / POOL);
        const float bh = fmaxf(c4 * scale - ay1, 1.0f) * (1.0f / POOL);

        // Normalized coords * scale <= 0.25 => samples in [0,1.18] => Y0 in {0,1}
        const int Y0 = (int)floorf(fminf(fmaxf(ay1 + 0.5f * bh, 0.0f), Hf - 1.0f));

        if (lane == 0)
            hdr_s = make_int4((int)bf * (CCH * H * H), H, Y0, lvl);

        if (lane < POOL) {
            const int   p  = lane;
            const float pc = (float)p + 0.5f;

            float wvy[3] = {0.f, 0.f, 0.f};
            {
                float y   = ay1 + pc * bh;
                float vy  = (y > -1.0f && y < Hf) ? 1.0f : 0.0f;
                float ycl = fminf(fmaxf(y, 0.0f), Hf - 1.0f);
                int   y0  = (int)floorf(ycl);
                float ly  = ycl - (float)y0;
                wvy[y0     - Y0] += vy * (1.0f - ly);
                wvy[y0 + 1 - Y0] += vy * ly;           // y0+1 <= 2 < H-1
            }
            float wvx[3] = {0.f, 0.f, 0.f};
            {
                float x   = ax1 + pc * bw;
                float vx  = (x > -1.0f && x < Hf) ? 1.0f : 0.0f;
                float xcl = fminf(fmaxf(x, 0.0f), Hf - 1.0f);
                int   x0  = (int)floorf(xcl);
                float lx  = xcl - (float)x0;
                wvx[x0    ] += vx * (1.0f - lx);
                wvx[x0 + 1] += vx * lx;                // x0+1 <= 2
            }

            float* wyf = (float*)&w_s[0];    // [4][3][2]
            float* wxf = (float*)&w_s[12];   // [7][3][2]
            if (p < 6) {
                const int j = p >> 1, h2 = p & 1;
                wyf[(j * 3 + 0) * 2 + h2] = wvy[0];
                wyf[(j * 3 + 1) * 2 + h2] = wvy[1];
                wyf[(j * 3 + 2) * 2 + h2] = wvy[2];
            } else {  // p == 6 -> pair (6,6): both halves
                wyf[(3 * 3 + 0) * 2 + 0] = wvy[0]; wyf[(3 * 3 + 0) * 2 + 1] = wvy[0];
                wyf[(3 * 3 + 1) * 2 + 0] = wvy[1]; wyf[(3 * 3 + 1) * 2 + 1] = wvy[1];
                wyf[(3 * 3 + 2) * 2 + 0] = wvy[2]; wyf[(3 * 3 + 2) * 2 + 1] = wvy[2];
            }
            wxf[(p * 3 + 0) * 2 + 0] = wvx[0]; wxf[(p * 3 + 0) * 2 + 1] = wvx[0];
            wxf[(p * 3 + 1) * 2 + 0] = wvx[1]; wxf[(p * 3 + 1) * 2 + 1] = wvx[1];
            wxf[(p * 3 + 2) * 2 + 0] = wvx[2]; wxf[(p * 3 + 2) * 2 + 1] = wvx[2];
        }
    }
    __syncthreads();

    // ---- Body (identical to split-k2, weights now from smem) ----
    const int4 hdr = hdr_s;                  // broadcast LDS
    const int  H = hdr.y, Y0 = hdr.z, lvl = hdr.w;

    const float* fm = (lvl == 2) ? f2 : (lvl == 3) ? f3 : (lvl == 4) ? f4 : f5;
    const int c = half * HALF + tid;
    const float* base = fm + (long)hdr.x + (long)c * (H * H) + Y0 * H;

    // Patch gather: 3 x LDG.128 issued immediately after the barrier.
    const float4 v0 = __ldg((const float4*)(base));
    const float4 v1 = __ldg((const float4*)(base + H));
    const float4 v2 = __ldg((const float4*)(base + 2 * H));

    // y-weights: 6 x LDS.128 (broadcast, conflict-free)
    u64 wy[12];
    {
        const ulonglong2* wv = (const ulonglong2*)&w_s[0];
        #pragma unroll
        for (int i = 0; i < 6; i++) {
            ulonglong2 t = wv[i];
            wy[2 * i]     = t.x;
            wy[2 * i + 1] = t.y;
        }
    }

    // Broadcast-pack patch columns.
    u64 vB[3][3];
    vB[0][0] = pk(v0.x, v0.x); vB[0][1] = pk(v0.y, v0.y); vB[0][2] = pk(v0.z, v0.z);
    vB[1][0] = pk(v1.x, v1.x); vB[1][1] = pk(v1.y, v1.y); vB[1][2] = pk(v1.z, v1.z);
    vB[2][0] = pk(v2.x, v2.x); vB[2][1] = pk(v2.y, v2.y); vB[2][2] = pk(v2.z, v2.z);

    // Row-reduce: tP[j][c] = packed (t_c(2j), t_c(2j+1)) — 36 FFMA2.
    u64 tP[4][3];
    #pragma unroll
    for (int j = 0; j < 4; j++) {
        const u64 wy0 = wy[j * 3 + 0], wy1 = wy[j * 3 + 1], wy2 = wy[j * 3 + 2];
        tP[j][0] = fma2(wy0, vB[0][0], fma2(wy1, vB[1][0], mul2(wy2, vB[2][0])));
        tP[j][1] = fma2(wy0, vB[0][1], fma2(wy1, vB[1][1], mul2(wy2, vB[2][1])));
        tP[j][2] = fma2(wy0, vB[0][2], fma2(wy1, vB[1][2], mul2(wy2, vB[2][2])));
    }

    // Col-reduce + store into this warp's stage chunk — 84 FFMA2.
    float* st = stage + tid * (POOL * POOL);
    #pragma unroll
    for (int px = 0; px < POOL; px++) {
        const u64 wx0 = w_s[12 + px * 3 + 0];
        const u64 wx1 = w_s[12 + px * 3 + 1];
        const u64 wx2 = w_s[12 + px * 3 + 2];
        #pragma unroll
        for (int j = 0; j < 4; j++) {
            u64 o = fma2(wx0, tP[j][0], fma2(wx1, tP[j][1], mul2(wx2, tP[j][2])));
            float lo, hi; unpk(o, lo, hi);
            if (j < 3) {
                st[(2 * j)     * POOL + px] = lo;
                st[(2 * j + 1) * POOL + px] = hi;
            } else {
                st[6 * POOL + px] = lo;   // pair (6,6): halves identical
            }
        }
    }
    __syncwarp();

    // Per-warp coalesced writeback (fire-and-forget STG.128).
    const float4* s4 = (const float4*)(stage + (wid * 32) * (POOL * POOL));
    float4*       o4 = (float4*)(out + ((long)box * CCH + half * HALF + wid * 32)
                                       * (POOL * POOL));
    #pragma unroll
    for (int k = 0; k < 13; k++) {
        const int idx = k * 32 + lane;
        if (idx < (32 * POOL * POOL) / 4)     // 392
            o4[idx] = s4[idx];
    }
}

extern "C" void kernel_launch(void* const* d_in, const int* in_sizes, int n_in,
                              void* d_out, int out_size)
{
    const float* boxes = (const float*)d_in[0];
    const float* f2    = (const float*)d_in[1];
    const float* f3    = (const float*)d_in[2];
    const float* f4    = (const float*)d_in[3];
    const float* f5    = (const float*)d_in[4];
    float*       out   = (float*)d_out;

    const int nboxes = in_sizes[0] / 5;
    roi_align_kernel<<<2 * nboxes, HALF>>>(boxes, f2, f3, f4, f5, out);
}